// round 4
// baseline (speedup 1.0000x reference)
#include <cuda_runtime.h>
#include <cuda_bf16.h>
#include <cstdint>

// ============================================================================
// TwoTowerModel fused kernel — mma.sync bf16 (3-term split), baseline sm_103 ISA
// (tcgen05 unavailable: harness PTX target is sm_103, not sm_103a)
// ============================================================================

static constexpr int BATCH   = 524288;
static constexpr int TILE    = 128;
static constexpr int NTILES  = BATCH / TILE;   // 4096
static constexpr int THREADS = 256;            // 8 warps, each owns 16 rows
static constexpr int NCTAS   = 148;

// ---- shared memory layout (bytes) ----
// X (gathered emb, split): [128 rows][64 cols] bf16, SW128-swizzled, 16KB each
static constexpr int OFF_XHI = 0;
static constexpr int OFF_XLO = 16384;
// H (layer-1 act, split): 2 k-buffers of [128][64] per level
//   hi: buf0 @ OFF_H, buf1 @ OFF_H+16384 ; lo: +32768
static constexpr int OFF_H   = 32768;          // 64KB total
// W1 fragments: [tower*2+level] * 16KB  (frag-linear: (kt*16+nt)*32+lane, 8B each)
static constexpr int OFF_W1F = 98304;          // 64KB
// W2 fragments: [tower*2+level] * 16KB  (frag-linear: (kt*8+nt)*32+lane, 8B each)
static constexpr int OFF_W2F = 163840;         // 64KB
static constexpr int OFF_B1  = 229376;         // float[2][128]
static constexpr int OFF_B2  = 230400;         // float[2][64]
static constexpr int SMEM_TOTAL = 230912;

__device__ __forceinline__ uint32_t smem_u32(const void* p) {
    uint32_t a;
    asm("{ .reg .u64 t; cvta.to.shared.u64 t, %1; cvt.u32.u64 %0, t; }" : "=r"(a) : "l"(p));
    return a;
}

// m16n8k16 row.col f32.bf16.bf16.f32 — baseline ISA, runs on tensor pipe (HMMA)
__device__ __forceinline__ void mma_bf16(float* d, const uint32_t* a, uint32_t b0, uint32_t b1) {
    asm volatile("mma.sync.aligned.m16n8k16.row.col.f32.bf16.bf16.f32 "
        "{%0,%1,%2,%3}, {%4,%5,%6,%7}, {%8,%9}, {%0,%1,%2,%3};"
        : "+f"(d[0]), "+f"(d[1]), "+f"(d[2]), "+f"(d[3])
        : "r"(a[0]), "r"(a[1]), "r"(a[2]), "r"(a[3]), "r"(b0), "r"(b1));
}

__device__ __forceinline__ void ldm4(uint32_t* a, uint32_t addr) {
    asm volatile("ldmatrix.sync.aligned.m8n8.x4.shared.b16 {%0,%1,%2,%3}, [%4];"
        : "=r"(a[0]), "=r"(a[1]), "=r"(a[2]), "=r"(a[3]) : "r"(addr) : "memory");
}

__device__ __forceinline__ void lds64(uint32_t& b0, uint32_t& b1, uint32_t addr) {
    asm volatile("ld.shared.v2.b32 {%0,%1}, [%2];" : "=r"(b0), "=r"(b1) : "r"(addr));
}

// pack two bf16 (low = first arg)
__device__ __forceinline__ uint32_t pack2(__nv_bfloat16 a, __nv_bfloat16 b) {
    return (uint32_t)__bfloat16_as_ushort(a) | ((uint32_t)__bfloat16_as_ushort(b) << 16);
}
// fp32 pair -> bf16 hi pair + bf16 residual pair
__device__ __forceinline__ void split2(float a, float b, uint32_t& hi, uint32_t& lo) {
    __nv_bfloat16 ah = __float2bfloat16(a);
    __nv_bfloat16 bh = __float2bfloat16(b);
    float ar = a - __bfloat162float(ah);
    float br = b - __bfloat162float(bh);
    hi = pack2(ah, bh);
    lo = pack2(__float2bfloat16(ar), __float2bfloat16(br));
}

__global__ __launch_bounds__(THREADS, 1)
void twotower_kernel(
    const int* __restrict__ user_ids, const int* __restrict__ item_ids,
    const float* __restrict__ user_table, const float* __restrict__ item_table,
    const float* __restrict__ uW1, const float* __restrict__ ub1,
    const float* __restrict__ uW2, const float* __restrict__ ub2,
    const float* __restrict__ iW1, const float* __restrict__ ib1,
    const float* __restrict__ iW2, const float* __restrict__ ib2,
    float* __restrict__ out)
{
    extern __shared__ char smem[];
    const uint32_t sb = smem_u32(smem);
    const int tid  = threadIdx.x;
    const int wid  = tid >> 5;
    const int lane = tid & 31;
    const int tg   = lane & 3;        // thread-in-group (n-col pair selector)
    const int g    = lane >> 2;       // group (row within 8)

    // ======================= stage weights as mma B-fragments =======================
    // B-frag for m16n8k16 .col: lane holds B[k0..k0+1][n] (reg b0) and B[k0+8..k0+9][n] (b1)
    // with n = nt*8 + g, k0 = kt*16 + tg*2. Stored frag-linear, 8B per lane.
    for (int t = 0; t < 2; t++) {
        const float* gW1 = t ? iW1 : uW1;   // [64][128] row-major
        const float* gW2 = t ? iW2 : uW2;   // [128][64]
        const float* gb1 = t ? ib1 : ub1;
        const float* gb2 = t ? ib2 : ub2;
        for (int p = tid; p < 2048; p += THREADS) {       // W1: kt(4) x nt(16) x lane(32)
            int kt = p >> 9, nt = (p >> 5) & 15, ln = p & 31;
            int ltg = ln & 3, lg = ln >> 2;
            int n = nt * 8 + lg, k0 = kt * 16 + ltg * 2;
            float w00 = __ldg(gW1 + k0 * 128 + n);
            float w01 = __ldg(gW1 + (k0 + 1) * 128 + n);
            float w10 = __ldg(gW1 + (k0 + 8) * 128 + n);
            float w11 = __ldg(gW1 + (k0 + 9) * 128 + n);
            uint32_t hA, lA, hB, lB;
            split2(w00, w01, hA, lA);
            split2(w10, w11, hB, lB);
            uint2* dhi = (uint2*)(smem + OFF_W1F + (t * 2 + 0) * 16384) + p;
            uint2* dlo = (uint2*)(smem + OFF_W1F + (t * 2 + 1) * 16384) + p;
            *dhi = make_uint2(hA, hB);
            *dlo = make_uint2(lA, lB);
        }
        for (int p = tid; p < 2048; p += THREADS) {       // W2: kt(8) x nt(8) x lane(32)
            int kt = p >> 8, nt = (p >> 5) & 7, ln = p & 31;
            int ltg = ln & 3, lg = ln >> 2;
            int n = nt * 8 + lg, k0 = kt * 16 + ltg * 2;
            float w00 = __ldg(gW2 + k0 * 64 + n);
            float w01 = __ldg(gW2 + (k0 + 1) * 64 + n);
            float w10 = __ldg(gW2 + (k0 + 8) * 64 + n);
            float w11 = __ldg(gW2 + (k0 + 9) * 64 + n);
            uint32_t hA, lA, hB, lB;
            split2(w00, w01, hA, lA);
            split2(w10, w11, hB, lB);
            uint2* dhi = (uint2*)(smem + OFF_W2F + (t * 2 + 0) * 16384) + p;
            uint2* dlo = (uint2*)(smem + OFF_W2F + (t * 2 + 1) * 16384) + p;
            *dhi = make_uint2(hA, hB);
            *dlo = make_uint2(lA, lB);
        }
        if (tid < 128) ((float*)(smem + OFF_B1))[t * 128 + tid] = __ldg(gb1 + tid);
        if (tid < 64)  ((float*)(smem + OFF_B2))[t * 64 + tid]  = __ldg(gb2 + tid);
    }
    __syncthreads();

    // per-lane ldmatrix row addressing (A fragments, 16-row warp slice)
    const int lr   = 16 * wid + (lane & 15);   // this lane's ldmatrix source row
    const int lrx  = lr & 7;
    const uint32_t lrb = (uint32_t)lr * 128;
    const int khalf = lane >> 4;               // 0: k0-7, 1: k8-15

    // epilogue row pair for this thread
    const int rA = 16 * wid + g;
    const int rB = rA + 8;
    const uint32_t rA7 = (uint32_t)(rA & 7), rB7 = (uint32_t)(rB & 7);
    const uint32_t rAb = (uint32_t)rA * 128, rBb = (uint32_t)rB * 128;

    // gather mapping: 2 threads per row, warp-local rows
    const int grow  = tid >> 1;                // row 0..127 (warp w covers 16w..16w+15)
    const int ghalf = tid & 1;                 // which 32-col half

    float uvec[8][4];                          // normalized user vec (this thread's slots)

    for (int tile = blockIdx.x; tile < NTILES; tile += gridDim.x) {
        const int rowbase = tile * TILE;
#pragma unroll
        for (int t = 0; t < 2; t++) {
            const int*   ids   = t ? item_ids   : user_ids;
            const float* table = t ? item_table : user_table;

            // ---- gather one embedding row-half, split to Xhi/Xlo (SW128) ----
            {
                int id = __ldg(ids + rowbase + grow);
                const float4* src = (const float4*)(table + (size_t)id * 64) + ghalf * 8;
#pragma unroll
                for (int j = 0; j < 4; j++) {            // 2 float4 -> one 16B bf16 chunk
                    float4 q0 = __ldg(src + 2 * j);
                    float4 q1 = __ldg(src + 2 * j + 1);
                    uint32_t h0, l0, h1, l1, h2, l2, h3, l3;
                    split2(q0.x, q0.y, h0, l0);
                    split2(q0.z, q0.w, h1, l1);
                    split2(q1.x, q1.y, h2, l2);
                    split2(q1.z, q1.w, h3, l3);
                    uint32_t c = (uint32_t)(ghalf * 4 + j);
                    uint32_t ad = (uint32_t)grow * 128 + ((c ^ ((uint32_t)grow & 7)) << 4);
                    *(uint4*)(smem + OFF_XHI + ad) = make_uint4(h0, h1, h2, h3);
                    *(uint4*)(smem + OFF_XLO + ad) = make_uint4(l0, l1, l2, l3);
                }
            }
            __syncwarp();

            // ---- GEMM1: D1[16 x 128] = X * W1, K=64, 3-term split ----
            float acc[16][4];
#pragma unroll
            for (int nt = 0; nt < 16; nt++)
#pragma unroll
                for (int j = 0; j < 4; j++) acc[nt][j] = 0.0f;

#pragma unroll
            for (int kt = 0; kt < 4; kt++) {
                uint32_t Ah[4], Al[4];
                uint32_t chg = (uint32_t)(kt * 2 + khalf);
                uint32_t aoff = lrb + ((chg ^ (uint32_t)lrx) << 4);
                ldm4(Ah, sb + OFF_XHI + aoff);
                ldm4(Al, sb + OFF_XLO + aoff);
                uint32_t bhB = sb + OFF_W1F + (uint32_t)(t * 2) * 16384 + ((uint32_t)(kt * 16) * 32 + lane) * 8;
                uint32_t blB = bhB + 16384;
#pragma unroll
                for (int nt = 0; nt < 16; nt++) {
                    uint32_t b0, b1;
                    lds64(b0, b1, bhB + (uint32_t)nt * 256);
                    mma_bf16(acc[nt], Ah, b0, b1);
                    mma_bf16(acc[nt], Al, b0, b1);
                    lds64(b0, b1, blB + (uint32_t)nt * 256);
                    mma_bf16(acc[nt], Ah, b0, b1);
                }
            }

            // ---- epilogue 1: bias + relu + split -> H (hi/lo, 2 k-buffers) ----
            {
                const float* b1p = (const float*)(smem + OFF_B1) + t * 128;
#pragma unroll
                for (int nt = 0; nt < 16; nt++) {
                    int c0 = nt * 8 + tg * 2;
                    float v0 = fmaxf(acc[nt][0] + b1p[c0],     0.0f);
                    float v1 = fmaxf(acc[nt][1] + b1p[c0 + 1], 0.0f);
                    float v2 = fmaxf(acc[nt][2] + b1p[c0],     0.0f);
                    float v3 = fmaxf(acc[nt][3] + b1p[c0 + 1], 0.0f);
                    uint32_t h01, l01, h23, l23;
                    split2(v0, v1, h01, l01);
                    split2(v2, v3, h23, l23);
                    int hb = OFF_H + (nt >> 3) * 16384;
                    int lb = hb + 32768;
                    uint32_t c = (uint32_t)(nt & 7);
                    uint32_t a0 = rAb + ((c ^ rA7) << 4) + (uint32_t)tg * 4;
                    uint32_t a1 = rBb + ((c ^ rB7) << 4) + (uint32_t)tg * 4;
                    *(uint32_t*)(smem + hb + a0) = h01;
                    *(uint32_t*)(smem + hb + a1) = h23;
                    *(uint32_t*)(smem + lb + a0) = l01;
                    *(uint32_t*)(smem + lb + a1) = l23;
                }
            }
            __syncwarp();

            // ---- GEMM2: D2[16 x 64] = H * W2, K=128, 3-term split ----
            float acc2[8][4];
#pragma unroll
            for (int nt = 0; nt < 8; nt++)
#pragma unroll
                for (int j = 0; j < 4; j++) acc2[nt][j] = 0.0f;

#pragma unroll
            for (int kt = 0; kt < 8; kt++) {
                uint32_t Ah[4], Al[4];
                uint32_t hbase = sb + OFF_H + (uint32_t)(kt >> 2) * 16384;
                uint32_t chg = (uint32_t)((kt & 3) * 2 + khalf);
                uint32_t aoff = lrb + ((chg ^ (uint32_t)lrx) << 4);
                ldm4(Ah, hbase + aoff);
                ldm4(Al, hbase + 32768 + aoff);
                uint32_t bhB = sb + OFF_W2F + (uint32_t)(t * 2) * 16384 + ((uint32_t)(kt * 8) * 32 + lane) * 8;
                uint32_t blB = bhB + 16384;
#pragma unroll
                for (int nt = 0; nt < 8; nt++) {
                    uint32_t b0, b1;
                    lds64(b0, b1, bhB + (uint32_t)nt * 256);
                    mma_bf16(acc2[nt], Ah, b0, b1);
                    mma_bf16(acc2[nt], Al, b0, b1);
                    lds64(b0, b1, blB + (uint32_t)nt * 256);
                    mma_bf16(acc2[nt], Ah, b0, b1);
                }
            }

            // ---- epilogue 2: bias + relu + l2norm; user -> regs, item -> dot+store ----
            {
                const float* b2p = (const float*)(smem + OFF_B2) + t * 64;
                float ssA = 0.0f, ssB = 0.0f;
#pragma unroll
                for (int nt = 0; nt < 8; nt++) {
                    int c0 = nt * 8 + tg * 2;
                    acc2[nt][0] = fmaxf(acc2[nt][0] + b2p[c0],     0.0f);
                    acc2[nt][1] = fmaxf(acc2[nt][1] + b2p[c0 + 1], 0.0f);
                    acc2[nt][2] = fmaxf(acc2[nt][2] + b2p[c0],     0.0f);
                    acc2[nt][3] = fmaxf(acc2[nt][3] + b2p[c0 + 1], 0.0f);
                    ssA += acc2[nt][0] * acc2[nt][0] + acc2[nt][1] * acc2[nt][1];
                    ssB += acc2[nt][2] * acc2[nt][2] + acc2[nt][3] * acc2[nt][3];
                }
                ssA += __shfl_xor_sync(0xffffffffu, ssA, 1);
                ssA += __shfl_xor_sync(0xffffffffu, ssA, 2);
                ssB += __shfl_xor_sync(0xffffffffu, ssB, 1);
                ssB += __shfl_xor_sync(0xffffffffu, ssB, 2);
                float invA = 1.0f / fmaxf(sqrtf(ssA), 1e-12f);
                float invB = 1.0f / fmaxf(sqrtf(ssB), 1e-12f);
                if (t == 0) {
#pragma unroll
                    for (int nt = 0; nt < 8; nt++) {
                        uvec[nt][0] = acc2[nt][0] * invA;
                        uvec[nt][1] = acc2[nt][1] * invA;
                        uvec[nt][2] = acc2[nt][2] * invB;
                        uvec[nt][3] = acc2[nt][3] * invB;
                    }
                } else {
                    float dA = 0.0f, dB = 0.0f;
#pragma unroll
                    for (int nt = 0; nt < 8; nt++) {
                        dA += uvec[nt][0] * acc2[nt][0] + uvec[nt][1] * acc2[nt][1];
                        dB += uvec[nt][2] * acc2[nt][2] + uvec[nt][3] * acc2[nt][3];
                    }
                    dA *= invA;
                    dB *= invB;
                    dA += __shfl_xor_sync(0xffffffffu, dA, 1);
                    dA += __shfl_xor_sync(0xffffffffu, dA, 2);
                    dB += __shfl_xor_sync(0xffffffffu, dB, 1);
                    dB += __shfl_xor_sync(0xffffffffu, dB, 2);
                    if (tg == 0) {
                        out[rowbase + rA] = dA;
                        out[rowbase + rB] = dB;
                    }
                }
            }
            __syncwarp();
        }
    }
}

extern "C" void kernel_launch(void* const* d_in, const int* in_sizes, int n_in,
                              void* d_out, int out_size) {
    const int*   user_ids   = (const int*)d_in[0];
    const int*   item_ids   = (const int*)d_in[1];
    const float* user_table = (const float*)d_in[2];
    const float* item_table = (const float*)d_in[3];
    const float* uW1 = (const float*)d_in[4];
    const float* ub1 = (const float*)d_in[5];
    const float* uW2 = (const float*)d_in[6];
    const float* ub2 = (const float*)d_in[7];
    const float* iW1 = (const float*)d_in[8];
    const float* ib1 = (const float*)d_in[9];
    const float* iW2 = (const float*)d_in[10];
    const float* ib2 = (const float*)d_in[11];
    float* out = (float*)d_out;

    cudaFuncSetAttribute(twotower_kernel, cudaFuncAttributeMaxDynamicSharedMemorySize, SMEM_TOTAL);
    twotower_kernel<<<NCTAS, THREADS, SMEM_TOTAL>>>(
        user_ids, item_ids, user_table, item_table,
        uW1, ub1, uW2, ub2, iW1, ib1, iW2, ib2, out);
}

// round 6
// speedup vs baseline: 1.3539x; 1.3539x over previous
#include <cuda_runtime.h>
#include <cuda_fp16.h>
#include <cstdint>

// ============================================================================
// TwoTowerModel fused kernel — mma.sync fp16 2-term split + pipelined gather
// (baseline sm_103 ISA: no tcgen05 — harness PTX target is sm_103)
// ============================================================================

static constexpr int BATCH   = 524288;
static constexpr int TILE    = 128;
static constexpr int NTILES  = BATCH / TILE;   // 4096
static constexpr int THREADS = 256;            // 8 warps, each owns 16 rows
static constexpr int NCTAS   = 148;

// ---- shared memory layout (bytes) ----
static constexpr int OFF_XU   = 0;             // user emb fp16 [128][64] swizzled, 16K
static constexpr int OFF_XI   = 16384;         // item emb fp16, 16K
static constexpr int OFF_H    = 32768;         // layer-1 act fp16 [128][128] as 2x16K
static constexpr int OFF_UVEC = 65536;         // normalized user vec f32 [128][64], 32K
static constexpr int OFF_W1F  = 98304;         // W1 frags: [tower*2+lev]*16K = 64K
static constexpr int OFF_W2F  = 163840;        // W2 frags: 64K
static constexpr int OFF_B1   = 229376;        // float[2][128]
static constexpr int OFF_B2   = 230400;        // float[2][64]
static constexpr int SMEM_TOTAL = 230912;

__device__ __forceinline__ uint32_t smem_u32(const void* p) {
    uint32_t a;
    asm("{ .reg .u64 t; cvta.to.shared.u64 t, %1; cvt.u32.u64 %0, t; }" : "=r"(a) : "l"(p));
    return a;
}

// m16n8k16 row.col f32.f16.f16.f32 — baseline ISA, tensor pipe (HMMA)
__device__ __forceinline__ void mma_f16(float* d, const uint32_t* a, uint32_t b0, uint32_t b1) {
    asm volatile("mma.sync.aligned.m16n8k16.row.col.f32.f16.f16.f32 "
        "{%0,%1,%2,%3}, {%4,%5,%6,%7}, {%8,%9}, {%0,%1,%2,%3};"
        : "+f"(d[0]), "+f"(d[1]), "+f"(d[2]), "+f"(d[3])
        : "r"(a[0]), "r"(a[1]), "r"(a[2]), "r"(a[3]), "r"(b0), "r"(b1));
}

__device__ __forceinline__ void ldm4(uint32_t* a, uint32_t addr) {
    asm volatile("ldmatrix.sync.aligned.m8n8.x4.shared.b16 {%0,%1,%2,%3}, [%4];"
        : "=r"(a[0]), "=r"(a[1]), "=r"(a[2]), "=r"(a[3]) : "r"(addr) : "memory");
}

__device__ __forceinline__ void lds64(uint32_t& b0, uint32_t& b1, uint32_t addr) {
    asm volatile("ld.shared.v2.b32 {%0,%1}, [%2];" : "=r"(b0), "=r"(b1) : "r"(addr));
}

__device__ __forceinline__ uint32_t packh2(float a, float b) {
    __half2 h = __floats2half2_rn(a, b);
    return *(uint32_t*)&h;
}
// fp32 pair -> fp16 hi pair + fp16 residual pair (for weights)
__device__ __forceinline__ void splith2(float a, float b, uint32_t& hi, uint32_t& lo) {
    __half ah = __float2half_rn(a);
    __half bh = __float2half_rn(b);
    float ar = a - __half2float(ah);
    float br = b - __half2float(bh);
    hi = (uint32_t)__half_as_ushort(ah) | ((uint32_t)__half_as_ushort(bh) << 16);
    lo = packh2(ar, br);
}

__global__ __launch_bounds__(THREADS, 1)
void twotower_kernel(
    const int* __restrict__ user_ids, const int* __restrict__ item_ids,
    const float* __restrict__ user_table, const float* __restrict__ item_table,
    const float* __restrict__ uW1, const float* __restrict__ ub1,
    const float* __restrict__ uW2, const float* __restrict__ ub2,
    const float* __restrict__ iW1, const float* __restrict__ ib1,
    const float* __restrict__ iW2, const float* __restrict__ ib2,
    float* __restrict__ out)
{
    extern __shared__ char smem[];
    const uint32_t sb = smem_u32(smem);
    const int tid  = threadIdx.x;
    const int wid  = tid >> 5;
    const int lane = tid & 31;
    const int tg   = lane & 3;
    const int g    = lane >> 2;

    // ======================= stage weights as mma B-fragments (fp16 hi/lo) ====
    for (int t = 0; t < 2; t++) {
        const float* gW1 = t ? iW1 : uW1;   // [64][128] row-major
        const float* gW2 = t ? iW2 : uW2;   // [128][64]
        const float* gb1 = t ? ib1 : ub1;
        const float* gb2 = t ? ib2 : ub2;
        for (int p = tid; p < 2048; p += THREADS) {       // W1: kt(4) x nt(16) x lane(32)
            int kt = p >> 9, nt = (p >> 5) & 15, ln = p & 31;
            int ltg = ln & 3, lg = ln >> 2;
            int n = nt * 8 + lg, k0 = kt * 16 + ltg * 2;
            float w00 = __ldg(gW1 + k0 * 128 + n);
            float w01 = __ldg(gW1 + (k0 + 1) * 128 + n);
            float w10 = __ldg(gW1 + (k0 + 8) * 128 + n);
            float w11 = __ldg(gW1 + (k0 + 9) * 128 + n);
            uint32_t hA, lA, hB, lB;
            splith2(w00, w01, hA, lA);
            splith2(w10, w11, hB, lB);
            uint2* dhi = (uint2*)(smem + OFF_W1F + (t * 2 + 0) * 16384) + p;
            uint2* dlo = (uint2*)(smem + OFF_W1F + (t * 2 + 1) * 16384) + p;
            *dhi = make_uint2(hA, hB);
            *dlo = make_uint2(lA, lB);
        }
        for (int p = tid; p < 2048; p += THREADS) {       // W2: kt(8) x nt(8) x lane(32)
            int kt = p >> 8, nt = (p >> 5) & 7, ln = p & 31;
            int ltg = ln & 3, lg = ln >> 2;
            int n = nt * 8 + lg, k0 = kt * 16 + ltg * 2;
            float w00 = __ldg(gW2 + k0 * 64 + n);
            float w01 = __ldg(gW2 + (k0 + 1) * 64 + n);
            float w10 = __ldg(gW2 + (k0 + 8) * 64 + n);
            float w11 = __ldg(gW2 + (k0 + 9) * 64 + n);
            uint32_t hA, lA, hB, lB;
            splith2(w00, w01, hA, lA);
            splith2(w10, w11, hB, lB);
            uint2* dhi = (uint2*)(smem + OFF_W2F + (t * 2 + 0) * 16384) + p;
            uint2* dlo = (uint2*)(smem + OFF_W2F + (t * 2 + 1) * 16384) + p;
            *dhi = make_uint2(hA, hB);
            *dlo = make_uint2(lA, lB);
        }
        if (tid < 128) ((float*)(smem + OFF_B1))[t * 128 + tid] = __ldg(gb1 + tid);
        if (tid < 64)  ((float*)(smem + OFF_B2))[t * 64 + tid]  = __ldg(gb2 + tid);
    }
    __syncthreads();

    // per-lane ldmatrix row addressing
    const int lr   = 16 * wid + (lane & 15);
    const int lrx  = lr & 7;
    const uint32_t lrb = (uint32_t)lr * 128;
    const int khalf = lane >> 4;

    // epilogue row pair
    const int rA = 16 * wid + g;
    const int rB = rA + 8;
    const uint32_t rA7 = (uint32_t)(rA & 7), rB7 = (uint32_t)(rB & 7);
    const uint32_t rAb = (uint32_t)rA * 128, rBb = (uint32_t)rB * 128;

    // gather mapping: 2 threads per row, warp-local rows
    const int grow  = tid >> 1;
    const int ghalf = tid & 1;

    // ---------------- prologue: prefetch tile0 user rows + item id ----------------
    int tile = blockIdx.x;
    float4 uf4[8];
    {
        int uid = __ldg(user_ids + tile * TILE + grow);
        const float4* usrc = (const float4*)(user_table + (size_t)uid * 64) + ghalf * 8;
#pragma unroll
        for (int j = 0; j < 8; j++) uf4[j] = __ldg(usrc + j);
    }
    int iid_hold = __ldg(item_ids + tile * TILE + grow);

    for (; tile < NTILES; tile += gridDim.x) {
        const int rowbase = tile * TILE;
        int tnext = tile + (int)gridDim.x;
        if (tnext >= NTILES) tnext = tile;   // harmless reload on last iteration

        // ---- 1. convert prefetched user rows -> XU (fp16, SW128) ----
#pragma unroll
        for (int j = 0; j < 4; j++) {
            float4 q0 = uf4[2 * j], q1 = uf4[2 * j + 1];
            uint32_t a = packh2(q0.x, q0.y), b = packh2(q0.z, q0.w);
            uint32_t c = packh2(q1.x, q1.y), d = packh2(q1.z, q1.w);
            uint32_t ch = (uint32_t)(ghalf * 4 + j);
            uint32_t ad = (uint32_t)grow * 128 + ((ch ^ ((uint32_t)grow & 7)) << 4);
            *(uint4*)(smem + OFF_XU + ad) = make_uint4(a, b, c, d);
        }
        __syncwarp();

        // ---- 2. issue item gather LDGs (hide under user GEMM1) ----
        float4 if4[8];
        {
            const float4* isrc = (const float4*)(item_table + (size_t)iid_hold * 64) + ghalf * 8;
#pragma unroll
            for (int j = 0; j < 8; j++) if4[j] = __ldg(isrc + j);
        }
        // ---- 3. prefetch next-tile ids ----
        int uid_next = __ldg(user_ids + tnext * TILE + grow);
        int iid_next = __ldg(item_ids + tnext * TILE + grow);

        // ================= USER tower =================
        // ---- GEMM1: D1[16x128] = XU * W1u, K=64, 2-term fp16 ----
        float acc[16][4];
#pragma unroll
        for (int nt = 0; nt < 16; nt++)
#pragma unroll
            for (int j = 0; j < 4; j++) acc[nt][j] = 0.0f;
#pragma unroll
        for (int kt = 0; kt < 4; kt++) {
            uint32_t A[4];
            uint32_t chg = (uint32_t)(kt * 2 + khalf);
            ldm4(A, sb + OFF_XU + lrb + ((chg ^ (uint32_t)lrx) << 4));
            uint32_t bh = sb + OFF_W1F + ((uint32_t)(kt * 16) * 32 + lane) * 8;
            uint32_t bl = bh + 16384;
#pragma unroll
            for (int nt = 0; nt < 16; nt++) {
                uint32_t b0, b1;
                lds64(b0, b1, bh + (uint32_t)nt * 256);
                mma_f16(acc[nt], A, b0, b1);
                lds64(b0, b1, bl + (uint32_t)nt * 256);
                mma_f16(acc[nt], A, b0, b1);
            }
        }
        // ---- epilogue 1: bias + relu -> H fp16 ----
        {
            const float* b1p = (const float*)(smem + OFF_B1);
#pragma unroll
            for (int nt = 0; nt < 16; nt++) {
                int c0 = nt * 8 + tg * 2;
                float v0 = fmaxf(acc[nt][0] + b1p[c0],     0.0f);
                float v1 = fmaxf(acc[nt][1] + b1p[c0 + 1], 0.0f);
                float v2 = fmaxf(acc[nt][2] + b1p[c0],     0.0f);
                float v3 = fmaxf(acc[nt][3] + b1p[c0 + 1], 0.0f);
                int hb = OFF_H + (nt >> 3) * 16384;
                uint32_t cc = (uint32_t)(nt & 7);
                *(uint32_t*)(smem + hb + rAb + ((cc ^ rA7) << 4) + (uint32_t)tg * 4) = packh2(v0, v1);
                *(uint32_t*)(smem + hb + rBb + ((cc ^ rB7) << 4) + (uint32_t)tg * 4) = packh2(v2, v3);
            }
        }
        __syncwarp();

        // ---- 5. convert item rows -> XI (data arrived during GEMM1) ----
#pragma unroll
        for (int j = 0; j < 4; j++) {
            float4 q0 = if4[2 * j], q1 = if4[2 * j + 1];
            uint32_t a = packh2(q0.x, q0.y), b = packh2(q0.z, q0.w);
            uint32_t c = packh2(q1.x, q1.y), d = packh2(q1.z, q1.w);
            uint32_t ch = (uint32_t)(ghalf * 4 + j);
            uint32_t ad = (uint32_t)grow * 128 + ((ch ^ ((uint32_t)grow & 7)) << 4);
            *(uint4*)(smem + OFF_XI + ad) = make_uint4(a, b, c, d);
        }
        __syncwarp();

        // ---- 6. issue next-tile user gather LDGs (hide under GEMM2 + item tower) ----
        {
            const float4* usrc = (const float4*)(user_table + (size_t)uid_next * 64) + ghalf * 8;
#pragma unroll
            for (int j = 0; j < 8; j++) uf4[j] = __ldg(usrc + j);
        }

        // ---- GEMM2 user: D2[16x64] = H * W2u, K=128 ----
        float acc2[8][4];
#pragma unroll
        for (int nt = 0; nt < 8; nt++)
#pragma unroll
            for (int j = 0; j < 4; j++) acc2[nt][j] = 0.0f;
#pragma unroll
        for (int kt = 0; kt < 8; kt++) {
            uint32_t A[4];
            uint32_t hbase = sb + OFF_H + (uint32_t)(kt >> 2) * 16384;
            uint32_t chg = (uint32_t)((kt & 3) * 2 + khalf);
            ldm4(A, hbase + lrb + ((chg ^ (uint32_t)lrx) << 4));
            uint32_t bh = sb + OFF_W2F + ((uint32_t)(kt * 8) * 32 + lane) * 8;
            uint32_t bl = bh + 16384;
#pragma unroll
            for (int nt = 0; nt < 8; nt++) {
                uint32_t b0, b1;
                lds64(b0, b1, bh + (uint32_t)nt * 256);
                mma_f16(acc2[nt], A, b0, b1);
                lds64(b0, b1, bl + (uint32_t)nt * 256);
                mma_f16(acc2[nt], A, b0, b1);
            }
        }
        // ---- epilogue 2 user: bias + relu + l2norm -> UVEC smem ----
        {
            const float* b2p = (const float*)(smem + OFF_B2);
            float ssA = 0.0f, ssB = 0.0f;
#pragma unroll
            for (int nt = 0; nt < 8; nt++) {
                int c0 = nt * 8 + tg * 2;
                acc2[nt][0] = fmaxf(acc2[nt][0] + b2p[c0],     0.0f);
                acc2[nt][1] = fmaxf(acc2[nt][1] + b2p[c0 + 1], 0.0f);
                acc2[nt][2] = fmaxf(acc2[nt][2] + b2p[c0],     0.0f);
                acc2[nt][3] = fmaxf(acc2[nt][3] + b2p[c0 + 1], 0.0f);
                ssA += acc2[nt][0] * acc2[nt][0] + acc2[nt][1] * acc2[nt][1];
                ssB += acc2[nt][2] * acc2[nt][2] + acc2[nt][3] * acc2[nt][3];
            }
            ssA += __shfl_xor_sync(0xffffffffu, ssA, 1);
            ssA += __shfl_xor_sync(0xffffffffu, ssA, 2);
            ssB += __shfl_xor_sync(0xffffffffu, ssB, 1);
            ssB += __shfl_xor_sync(0xffffffffu, ssB, 2);
            float invA = 1.0f / fmaxf(sqrtf(ssA), 1e-12f);
            float invB = 1.0f / fmaxf(sqrtf(ssB), 1e-12f);
#pragma unroll
            for (int nt = 0; nt < 8; nt++) {
                int c0 = nt * 8 + tg * 2;
                int cA = c0 ^ ((rA & 7) << 3);
                int cB = c0 ^ ((rB & 7) << 3);
                float2 vA = make_float2(acc2[nt][0] * invA, acc2[nt][1] * invA);
                float2 vB = make_float2(acc2[nt][2] * invB, acc2[nt][3] * invB);
                *(float2*)(smem + OFF_UVEC + ((uint32_t)(rA * 64 + cA) << 2)) = vA;
                *(float2*)(smem + OFF_UVEC + ((uint32_t)(rB * 64 + cB) << 2)) = vB;
            }
        }
        __syncwarp();

        // ================= ITEM tower =================
        // ---- GEMM1 item (XI) ----
#pragma unroll
        for (int nt = 0; nt < 16; nt++)
#pragma unroll
            for (int j = 0; j < 4; j++) acc[nt][j] = 0.0f;
#pragma unroll
        for (int kt = 0; kt < 4; kt++) {
            uint32_t A[4];
            uint32_t chg = (uint32_t)(kt * 2 + khalf);
            ldm4(A, sb + OFF_XI + lrb + ((chg ^ (uint32_t)lrx) << 4));
            uint32_t bh = sb + OFF_W1F + 2u * 16384 + ((uint32_t)(kt * 16) * 32 + lane) * 8;
            uint32_t bl = bh + 16384;
#pragma unroll
            for (int nt = 0; nt < 16; nt++) {
                uint32_t b0, b1;
                lds64(b0, b1, bh + (uint32_t)nt * 256);
                mma_f16(acc[nt], A, b0, b1);
                lds64(b0, b1, bl + (uint32_t)nt * 256);
                mma_f16(acc[nt], A, b0, b1);
            }
        }
        {
            const float* b1p = (const float*)(smem + OFF_B1) + 128;
#pragma unroll
            for (int nt = 0; nt < 16; nt++) {
                int c0 = nt * 8 + tg * 2;
                float v0 = fmaxf(acc[nt][0] + b1p[c0],     0.0f);
                float v1 = fmaxf(acc[nt][1] + b1p[c0 + 1], 0.0f);
                float v2 = fmaxf(acc[nt][2] + b1p[c0],     0.0f);
                float v3 = fmaxf(acc[nt][3] + b1p[c0 + 1], 0.0f);
                int hb = OFF_H + (nt >> 3) * 16384;
                uint32_t cc = (uint32_t)(nt & 7);
                *(uint32_t*)(smem + hb + rAb + ((cc ^ rA7) << 4) + (uint32_t)tg * 4) = packh2(v0, v1);
                *(uint32_t*)(smem + hb + rBb + ((cc ^ rB7) << 4) + (uint32_t)tg * 4) = packh2(v2, v3);
            }
        }
        __syncwarp();

        // ---- GEMM2 item ----
#pragma unroll
        for (int nt = 0; nt < 8; nt++)
#pragma unroll
            for (int j = 0; j < 4; j++) acc2[nt][j] = 0.0f;
#pragma unroll
        for (int kt = 0; kt < 8; kt++) {
            uint32_t A[4];
            uint32_t hbase = sb + OFF_H + (uint32_t)(kt >> 2) * 16384;
            uint32_t chg = (uint32_t)((kt & 3) * 2 + khalf);
            ldm4(A, hbase + lrb + ((chg ^ (uint32_t)lrx) << 4));
            uint32_t bh = sb + OFF_W2F + 2u * 16384 + ((uint32_t)(kt * 8) * 32 + lane) * 8;
            uint32_t bl = bh + 16384;
#pragma unroll
            for (int nt = 0; nt < 8; nt++) {
                uint32_t b0, b1;
                lds64(b0, b1, bh + (uint32_t)nt * 256);
                mma_f16(acc2[nt], A, b0, b1);
                lds64(b0, b1, bl + (uint32_t)nt * 256);
                mma_f16(acc2[nt], A, b0, b1);
            }
        }
        // ---- epilogue 2 item: bias + relu + l2norm + dot(UVEC) + store ----
        {
            const float* b2p = (const float*)(smem + OFF_B2) + 64;
            float ssA = 0.0f, ssB = 0.0f;
#pragma unroll
            for (int nt = 0; nt < 8; nt++) {
                int c0 = nt * 8 + tg * 2;
                acc2[nt][0] = fmaxf(acc2[nt][0] + b2p[c0],     0.0f);
                acc2[nt][1] = fmaxf(acc2[nt][1] + b2p[c0 + 1], 0.0f);
                acc2[nt][2] = fmaxf(acc2[nt][2] + b2p[c0],     0.0f);
                acc2[nt][3] = fmaxf(acc2[nt][3] + b2p[c0 + 1], 0.0f);
                ssA += acc2[nt][0] * acc2[nt][0] + acc2[nt][1] * acc2[nt][1];
                ssB += acc2[nt][2] * acc2[nt][2] + acc2[nt][3] * acc2[nt][3];
            }
            ssA += __shfl_xor_sync(0xffffffffu, ssA, 1);
            ssA += __shfl_xor_sync(0xffffffffu, ssA, 2);
            ssB += __shfl_xor_sync(0xffffffffu, ssB, 1);
            ssB += __shfl_xor_sync(0xffffffffu, ssB, 2);
            float invA = 1.0f / fmaxf(sqrtf(ssA), 1e-12f);
            float invB = 1.0f / fmaxf(sqrtf(ssB), 1e-12f);
            float dA = 0.0f, dB = 0.0f;
#pragma unroll
            for (int nt = 0; nt < 8; nt++) {
                int c0 = nt * 8 + tg * 2;
                int cA = c0 ^ ((rA & 7) << 3);
                int cB = c0 ^ ((rB & 7) << 3);
                float2 uA = *(const float2*)(smem + OFF_UVEC + ((uint32_t)(rA * 64 + cA) << 2));
                float2 uB = *(const float2*)(smem + OFF_UVEC + ((uint32_t)(rB * 64 + cB) << 2));
                dA += uA.x * acc2[nt][0] + uA.y * acc2[nt][1];
                dB += uB.x * acc2[nt][2] + uB.y * acc2[nt][3];
            }
            dA *= invA;
            dB *= invB;
            dA += __shfl_xor_sync(0xffffffffu, dA, 1);
            dA += __shfl_xor_sync(0xffffffffu, dA, 2);
            dB += __shfl_xor_sync(0xffffffffu, dB, 1);
            dB += __shfl_xor_sync(0xffffffffu, dB, 2);
            if (tg == 0) {
                out[rowbase + rA] = dA;
                out[rowbase + rB] = dB;
            }
        }
        iid_hold = iid_next;
        __syncwarp();
    }
}

extern "C" void kernel_launch(void* const* d_in, const int* in_sizes, int n_in,
                              void* d_out, int out_size) {
    const int*   user_ids   = (const int*)d_in[0];
    const int*   item_ids   = (const int*)d_in[1];
    const float* user_table = (const float*)d_in[2];
    const float* item_table = (const float*)d_in[3];
    const float* uW1 = (const float*)d_in[4];
    const float* ub1 = (const float*)d_in[5];
    const float* uW2 = (const float*)d_in[6];
    const float* ub2 = (const float*)d_in[7];
    const float* iW1 = (const float*)d_in[8];
    const float* ib1 = (const float*)d_in[9];
    const float* iW2 = (const float*)d_in[10];
    const float* ib2 = (const float*)d_in[11];
    float* out = (float*)d_out;

    cudaFuncSetAttribute(twotower_kernel, cudaFuncAttributeMaxDynamicSharedMemorySize, SMEM_TOTAL);
    twotower_kernel<<<NCTAS, THREADS, SMEM_TOTAL>>>(
        user_ids, item_ids, user_table, item_table,
        uW1, ub1, uW2, ub2, iW1, ib1, iW2, ib2, out);
}

// round 7
// speedup vs baseline: 1.8154x; 1.3409x over previous
#include <cuda_runtime.h>
#include <cuda_fp16.h>
#include <cstdint>

// ============================================================================
// TwoTowerModel fused kernel — mma.sync fp16 single-term + pipelined gather
// (baseline sm_103 ISA: no tcgen05 — harness PTX target is sm_103)
// ============================================================================

static constexpr int BATCH   = 524288;
static constexpr int TILE    = 128;
static constexpr int NTILES  = BATCH / TILE;   // 4096
static constexpr int THREADS = 256;            // 8 warps, each owns 16 rows
static constexpr int NCTAS   = 148;

// ---- shared memory layout (bytes) ----
static constexpr int OFF_XU   = 0;             // user emb fp16 [128][64] swizzled, 16K
static constexpr int OFF_XI   = 16384;         // item emb fp16, 16K
static constexpr int OFF_H    = 32768;         // layer-1 act fp16 [128][128] as 2x16K
static constexpr int OFF_UVEC = 65536;         // normalized user vec f32 [128][64], 32K
static constexpr int OFF_W1F  = 98304;         // W1 frags (nt-paired): [tower]*16K = 32K
static constexpr int OFF_W2F  = 131072;        // W2 frags: 32K
static constexpr int OFF_B1   = 163840;        // float[2][128]
static constexpr int OFF_B2   = 164864;        // float[2][64]
static constexpr int SMEM_TOTAL = 165376;

__device__ __forceinline__ uint32_t smem_u32(const void* p) {
    uint32_t a;
    asm("{ .reg .u64 t; cvta.to.shared.u64 t, %1; cvt.u32.u64 %0, t; }" : "=r"(a) : "l"(p));
    return a;
}

// m16n8k16 row.col f32.f16.f16.f32 — baseline ISA, tensor pipe (HMMA)
__device__ __forceinline__ void mma_f16(float* d, const uint32_t* a, uint32_t b0, uint32_t b1) {
    asm volatile("mma.sync.aligned.m16n8k16.row.col.f32.f16.f16.f32 "
        "{%0,%1,%2,%3}, {%4,%5,%6,%7}, {%8,%9}, {%0,%1,%2,%3};"
        : "+f"(d[0]), "+f"(d[1]), "+f"(d[2]), "+f"(d[3])
        : "r"(a[0]), "r"(a[1]), "r"(a[2]), "r"(a[3]), "r"(b0), "r"(b1));
}

__device__ __forceinline__ void ldm4(uint32_t* a, uint32_t addr) {
    asm volatile("ldmatrix.sync.aligned.m8n8.x4.shared.b16 {%0,%1,%2,%3}, [%4];"
        : "=r"(a[0]), "=r"(a[1]), "=r"(a[2]), "=r"(a[3]) : "r"(addr) : "memory");
}

__device__ __forceinline__ void lds128(uint32_t* q, uint32_t addr) {
    asm volatile("ld.shared.v4.b32 {%0,%1,%2,%3}, [%4];"
        : "=r"(q[0]), "=r"(q[1]), "=r"(q[2]), "=r"(q[3]) : "r"(addr));
}

__device__ __forceinline__ uint32_t packh2(float a, float b) {
    __half2 h = __floats2half2_rn(a, b);
    return *(uint32_t*)&h;
}

__global__ __launch_bounds__(THREADS, 1)
void twotower_kernel(
    const int* __restrict__ user_ids, const int* __restrict__ item_ids,
    const float* __restrict__ user_table, const float* __restrict__ item_table,
    const float* __restrict__ uW1, const float* __restrict__ ub1,
    const float* __restrict__ uW2, const float* __restrict__ ub2,
    const float* __restrict__ iW1, const float* __restrict__ ib1,
    const float* __restrict__ iW2, const float* __restrict__ ib2,
    float* __restrict__ out)
{
    extern __shared__ char smem[];
    const uint32_t sb = smem_u32(smem);
    const int tid  = threadIdx.x;
    const int wid  = tid >> 5;
    const int lane = tid & 31;
    const int tg   = lane & 3;
    const int g    = lane >> 2;

    // ============ stage weights as nt-paired mma B-fragments (single fp16) ====
    // lane holds, for (kt, ntp): {b0(nt=2ntp), b1(nt=2ntp), b0(nt=2ntp+1), b1(nt=2ntp+1)}
    // b0 = W[k0..k0+1][n], b1 = W[k0+8..k0+9][n], n = nt*8 + (ln>>2), k0 = kt*16 + (ln&3)*2
    for (int t = 0; t < 2; t++) {
        const float* gW1 = t ? iW1 : uW1;   // [64][128] row-major
        const float* gW2 = t ? iW2 : uW2;   // [128][64]
        const float* gb1 = t ? ib1 : ub1;
        const float* gb2 = t ? ib2 : ub2;
        for (int p = tid; p < 1024; p += THREADS) {       // W1: kt(4) x ntp(8) x lane(32)
            int kt = p >> 8, ntp = (p >> 5) & 7, ln = p & 31;
            int ltg = ln & 3, lg = ln >> 2;
            int k0 = kt * 16 + ltg * 2;
            uint32_t q[4];
#pragma unroll
            for (int s = 0; s < 2; s++) {
                int n = (2 * ntp + s) * 8 + lg;
                q[2 * s + 0] = packh2(__ldg(gW1 + k0 * 128 + n),       __ldg(gW1 + (k0 + 1) * 128 + n));
                q[2 * s + 1] = packh2(__ldg(gW1 + (k0 + 8) * 128 + n), __ldg(gW1 + (k0 + 9) * 128 + n));
            }
            *((uint4*)(smem + OFF_W1F + t * 16384) + p) = make_uint4(q[0], q[1], q[2], q[3]);
        }
        for (int p = tid; p < 1024; p += THREADS) {       // W2: kt(8) x ntp(4) x lane(32)
            int kt = p >> 7, ntp = (p >> 5) & 3, ln = p & 31;
            int ltg = ln & 3, lg = ln >> 2;
            int k0 = kt * 16 + ltg * 2;
            uint32_t q[4];
#pragma unroll
            for (int s = 0; s < 2; s++) {
                int n = (2 * ntp + s) * 8 + lg;
                q[2 * s + 0] = packh2(__ldg(gW2 + k0 * 64 + n),       __ldg(gW2 + (k0 + 1) * 64 + n));
                q[2 * s + 1] = packh2(__ldg(gW2 + (k0 + 8) * 64 + n), __ldg(gW2 + (k0 + 9) * 64 + n));
            }
            *((uint4*)(smem + OFF_W2F + t * 16384) + p) = make_uint4(q[0], q[1], q[2], q[3]);
        }
        if (tid < 128) ((float*)(smem + OFF_B1))[t * 128 + tid] = __ldg(gb1 + tid);
        if (tid < 64)  ((float*)(smem + OFF_B2))[t * 64 + tid]  = __ldg(gb2 + tid);
    }
    __syncthreads();

    // per-lane ldmatrix row addressing
    const int lr   = 16 * wid + (lane & 15);
    const int lrx  = lr & 7;
    const uint32_t lrb = (uint32_t)lr * 128;
    const int khalf = lane >> 4;

    // epilogue row pair
    const int rA = 16 * wid + g;
    const int rB = rA + 8;
    const uint32_t rA7 = (uint32_t)(rA & 7), rB7 = (uint32_t)(rB & 7);
    const uint32_t rAb = (uint32_t)rA * 128, rBb = (uint32_t)rB * 128;

    // gather mapping: 2 threads per row, warp-local rows
    const int grow  = tid >> 1;
    const int ghalf = tid & 1;

    // ---------------- prologue: prefetch tile0 user rows + item id ----------------
    int tile = blockIdx.x;
    float4 uf4[8];
    {
        int uid = __ldg(user_ids + tile * TILE + grow);
        const float4* usrc = (const float4*)(user_table + (size_t)uid * 64) + ghalf * 8;
#pragma unroll
        for (int j = 0; j < 8; j++) uf4[j] = __ldg(usrc + j);
    }
    int iid_hold = __ldg(item_ids + tile * TILE + grow);

    for (; tile < NTILES; tile += gridDim.x) {
        const int rowbase = tile * TILE;
        int tnext = tile + (int)gridDim.x;
        if (tnext >= NTILES) tnext = tile;   // harmless reload on last iteration

        // ---- 1. convert prefetched user rows -> XU (fp16, SW128) ----
#pragma unroll
        for (int j = 0; j < 4; j++) {
            float4 q0 = uf4[2 * j], q1 = uf4[2 * j + 1];
            uint32_t a = packh2(q0.x, q0.y), b = packh2(q0.z, q0.w);
            uint32_t c = packh2(q1.x, q1.y), d = packh2(q1.z, q1.w);
            uint32_t ch = (uint32_t)(ghalf * 4 + j);
            uint32_t ad = (uint32_t)grow * 128 + ((ch ^ ((uint32_t)grow & 7)) << 4);
            *(uint4*)(smem + OFF_XU + ad) = make_uint4(a, b, c, d);
        }
        __syncwarp();

        // ---- 2. issue item gather LDGs (hide under user GEMM1) ----
        float4 if4[8];
        {
            const float4* isrc = (const float4*)(item_table + (size_t)iid_hold * 64) + ghalf * 8;
#pragma unroll
            for (int j = 0; j < 8; j++) if4[j] = __ldg(isrc + j);
        }
        // ---- 3. prefetch next-tile ids ----
        int uid_next = __ldg(user_ids + tnext * TILE + grow);
        int iid_next = __ldg(item_ids + tnext * TILE + grow);

        // ================= USER tower =================
        // ---- GEMM1: D1[16x128] = XU * W1u, K=64, single fp16 ----
        float acc[16][4];
#pragma unroll
        for (int nt = 0; nt < 16; nt++)
#pragma unroll
            for (int j = 0; j < 4; j++) acc[nt][j] = 0.0f;
#pragma unroll
        for (int kt = 0; kt < 4; kt++) {
            uint32_t A[4];
            uint32_t chg = (uint32_t)(kt * 2 + khalf);
            ldm4(A, sb + OFF_XU + lrb + ((chg ^ (uint32_t)lrx) << 4));
            uint32_t wb = sb + OFF_W1F + ((uint32_t)(kt * 8 * 32 + lane)) * 16;
#pragma unroll
            for (int ntp = 0; ntp < 8; ntp++) {
                uint32_t q[4];
                lds128(q, wb + (uint32_t)ntp * 512);
                mma_f16(acc[2 * ntp],     A, q[0], q[1]);
                mma_f16(acc[2 * ntp + 1], A, q[2], q[3]);
            }
        }
        // ---- epilogue 1: bias + relu -> H fp16 ----
        {
            const float* b1p = (const float*)(smem + OFF_B1);
#pragma unroll
            for (int nt = 0; nt < 16; nt++) {
                int c0 = nt * 8 + tg * 2;
                float v0 = fmaxf(acc[nt][0] + b1p[c0],     0.0f);
                float v1 = fmaxf(acc[nt][1] + b1p[c0 + 1], 0.0f);
                float v2 = fmaxf(acc[nt][2] + b1p[c0],     0.0f);
                float v3 = fmaxf(acc[nt][3] + b1p[c0 + 1], 0.0f);
                int hb = OFF_H + (nt >> 3) * 16384;
                uint32_t cc = (uint32_t)(nt & 7);
                *(uint32_t*)(smem + hb + rAb + ((cc ^ rA7) << 4) + (uint32_t)tg * 4) = packh2(v0, v1);
                *(uint32_t*)(smem + hb + rBb + ((cc ^ rB7) << 4) + (uint32_t)tg * 4) = packh2(v2, v3);
            }
        }
        __syncwarp();

        // ---- 5. convert item rows -> XI (data arrived during GEMM1) ----
#pragma unroll
        for (int j = 0; j < 4; j++) {
            float4 q0 = if4[2 * j], q1 = if4[2 * j + 1];
            uint32_t a = packh2(q0.x, q0.y), b = packh2(q0.z, q0.w);
            uint32_t c = packh2(q1.x, q1.y), d = packh2(q1.z, q1.w);
            uint32_t ch = (uint32_t)(ghalf * 4 + j);
            uint32_t ad = (uint32_t)grow * 128 + ((ch ^ ((uint32_t)grow & 7)) << 4);
            *(uint4*)(smem + OFF_XI + ad) = make_uint4(a, b, c, d);
        }
        __syncwarp();

        // ---- 6. issue next-tile user gather LDGs (hide under GEMM2 + item tower) ----
        {
            const float4* usrc = (const float4*)(user_table + (size_t)uid_next * 64) + ghalf * 8;
#pragma unroll
            for (int j = 0; j < 8; j++) uf4[j] = __ldg(usrc + j);
        }

        // ---- GEMM2 user: D2[16x64] = H * W2u, K=128 ----
        float acc2[8][4];
#pragma unroll
        for (int nt = 0; nt < 8; nt++)
#pragma unroll
            for (int j = 0; j < 4; j++) acc2[nt][j] = 0.0f;
#pragma unroll
        for (int kt = 0; kt < 8; kt++) {
            uint32_t A[4];
            uint32_t hbase = sb + OFF_H + (uint32_t)(kt >> 2) * 16384;
            uint32_t chg = (uint32_t)((kt & 3) * 2 + khalf);
            ldm4(A, hbase + lrb + ((chg ^ (uint32_t)lrx) << 4));
            uint32_t wb = sb + OFF_W2F + ((uint32_t)(kt * 4 * 32 + lane)) * 16;
#pragma unroll
            for (int ntp = 0; ntp < 4; ntp++) {
                uint32_t q[4];
                lds128(q, wb + (uint32_t)ntp * 512);
                mma_f16(acc2[2 * ntp],     A, q[0], q[1]);
                mma_f16(acc2[2 * ntp + 1], A, q[2], q[3]);
            }
        }
        // ---- epilogue 2 user: bias + relu + l2norm -> UVEC smem ----
        {
            const float* b2p = (const float*)(smem + OFF_B2);
            float ssA = 0.0f, ssB = 0.0f;
#pragma unroll
            for (int nt = 0; nt < 8; nt++) {
                int c0 = nt * 8 + tg * 2;
                acc2[nt][0] = fmaxf(acc2[nt][0] + b2p[c0],     0.0f);
                acc2[nt][1] = fmaxf(acc2[nt][1] + b2p[c0 + 1], 0.0f);
                acc2[nt][2] = fmaxf(acc2[nt][2] + b2p[c0],     0.0f);
                acc2[nt][3] = fmaxf(acc2[nt][3] + b2p[c0 + 1], 0.0f);
                ssA += acc2[nt][0] * acc2[nt][0] + acc2[nt][1] * acc2[nt][1];
                ssB += acc2[nt][2] * acc2[nt][2] + acc2[nt][3] * acc2[nt][3];
            }
            ssA += __shfl_xor_sync(0xffffffffu, ssA, 1);
            ssA += __shfl_xor_sync(0xffffffffu, ssA, 2);
            ssB += __shfl_xor_sync(0xffffffffu, ssB, 1);
            ssB += __shfl_xor_sync(0xffffffffu, ssB, 2);
            float invA = 1.0f / fmaxf(sqrtf(ssA), 1e-12f);
            float invB = 1.0f / fmaxf(sqrtf(ssB), 1e-12f);
#pragma unroll
            for (int nt = 0; nt < 8; nt++) {
                int c0 = nt * 8 + tg * 2;
                int cA = c0 ^ ((rA & 7) << 3);
                int cB = c0 ^ ((rB & 7) << 3);
                float2 vA = make_float2(acc2[nt][0] * invA, acc2[nt][1] * invA);
                float2 vB = make_float2(acc2[nt][2] * invB, acc2[nt][3] * invB);
                *(float2*)(smem + OFF_UVEC + ((uint32_t)(rA * 64 + cA) << 2)) = vA;
                *(float2*)(smem + OFF_UVEC + ((uint32_t)(rB * 64 + cB) << 2)) = vB;
            }
        }
        __syncwarp();

        // ================= ITEM tower =================
        // ---- GEMM1 item (XI) ----
#pragma unroll
        for (int nt = 0; nt < 16; nt++)
#pragma unroll
            for (int j = 0; j < 4; j++) acc[nt][j] = 0.0f;
#pragma unroll
        for (int kt = 0; kt < 4; kt++) {
            uint32_t A[4];
            uint32_t chg = (uint32_t)(kt * 2 + khalf);
            ldm4(A, sb + OFF_XI + lrb + ((chg ^ (uint32_t)lrx) << 4));
            uint32_t wb = sb + OFF_W1F + 16384u + ((uint32_t)(kt * 8 * 32 + lane)) * 16;
#pragma unroll
            for (int ntp = 0; ntp < 8; ntp++) {
                uint32_t q[4];
                lds128(q, wb + (uint32_t)ntp * 512);
                mma_f16(acc[2 * ntp],     A, q[0], q[1]);
                mma_f16(acc[2 * ntp + 1], A, q[2], q[3]);
            }
        }
        {
            const float* b1p = (const float*)(smem + OFF_B1) + 128;
#pragma unroll
            for (int nt = 0; nt < 16; nt++) {
                int c0 = nt * 8 + tg * 2;
                float v0 = fmaxf(acc[nt][0] + b1p[c0],     0.0f);
                float v1 = fmaxf(acc[nt][1] + b1p[c0 + 1], 0.0f);
                float v2 = fmaxf(acc[nt][2] + b1p[c0],     0.0f);
                float v3 = fmaxf(acc[nt][3] + b1p[c0 + 1], 0.0f);
                int hb = OFF_H + (nt >> 3) * 16384;
                uint32_t cc = (uint32_t)(nt & 7);
                *(uint32_t*)(smem + hb + rAb + ((cc ^ rA7) << 4) + (uint32_t)tg * 4) = packh2(v0, v1);
                *(uint32_t*)(smem + hb + rBb + ((cc ^ rB7) << 4) + (uint32_t)tg * 4) = packh2(v2, v3);
            }
        }
        __syncwarp();

        // ---- GEMM2 item ----
#pragma unroll
        for (int nt = 0; nt < 8; nt++)
#pragma unroll
            for (int j = 0; j < 4; j++) acc2[nt][j] = 0.0f;
#pragma unroll
        for (int kt = 0; kt < 8; kt++) {
            uint32_t A[4];
            uint32_t hbase = sb + OFF_H + (uint32_t)(kt >> 2) * 16384;
            uint32_t chg = (uint32_t)((kt & 3) * 2 + khalf);
            ldm4(A, hbase + lrb + ((chg ^ (uint32_t)lrx) << 4));
            uint32_t wb = sb + OFF_W2F + 16384u + ((uint32_t)(kt * 4 * 32 + lane)) * 16;
#pragma unroll
            for (int ntp = 0; ntp < 4; ntp++) {
                uint32_t q[4];
                lds128(q, wb + (uint32_t)ntp * 512);
                mma_f16(acc2[2 * ntp],     A, q[0], q[1]);
                mma_f16(acc2[2 * ntp + 1], A, q[2], q[3]);
            }
        }
        // ---- epilogue 2 item: bias + relu + l2norm + dot(UVEC) + store ----
        {
            const float* b2p = (const float*)(smem + OFF_B2) + 64;
            float ssA = 0.0f, ssB = 0.0f;
#pragma unroll
            for (int nt = 0; nt < 8; nt++) {
                int c0 = nt * 8 + tg * 2;
                acc2[nt][0] = fmaxf(acc2[nt][0] + b2p[c0],     0.0f);
                acc2[nt][1] = fmaxf(acc2[nt][1] + b2p[c0 + 1], 0.0f);
                acc2[nt][2] = fmaxf(acc2[nt][2] + b2p[c0],     0.0f);
                acc2[nt][3] = fmaxf(acc2[nt][3] + b2p[c0 + 1], 0.0f);
                ssA += acc2[nt][0] * acc2[nt][0] + acc2[nt][1] * acc2[nt][1];
                ssB += acc2[nt][2] * acc2[nt][2] + acc2[nt][3] * acc2[nt][3];
            }
            ssA += __shfl_xor_sync(0xffffffffu, ssA, 1);
            ssA += __shfl_xor_sync(0xffffffffu, ssA, 2);
            ssB += __shfl_xor_sync(0xffffffffu, ssB, 1);
            ssB += __shfl_xor_sync(0xffffffffu, ssB, 2);
            float invA = 1.0f / fmaxf(sqrtf(ssA), 1e-12f);
            float invB = 1.0f / fmaxf(sqrtf(ssB), 1e-12f);
            float dA = 0.0f, dB = 0.0f;
#pragma unroll
            for (int nt = 0; nt < 8; nt++) {
                int c0 = nt * 8 + tg * 2;
                int cA = c0 ^ ((rA & 7) << 3);
                int cB = c0 ^ ((rB & 7) << 3);
                float2 uA = *(const float2*)(smem + OFF_UVEC + ((uint32_t)(rA * 64 + cA) << 2));
                float2 uB = *(const float2*)(smem + OFF_UVEC + ((uint32_t)(rB * 64 + cB) << 2));
                dA += uA.x * acc2[nt][0] + uA.y * acc2[nt][1];
                dB += uB.x * acc2[nt][2] + uB.y * acc2[nt][3];
            }
            dA *= invA;
            dB *= invB;
            dA += __shfl_xor_sync(0xffffffffu, dA, 1);
            dA += __shfl_xor_sync(0xffffffffu, dA, 2);
            dB += __shfl_xor_sync(0xffffffffu, dB, 1);
            dB += __shfl_xor_sync(0xffffffffu, dB, 2);
            if (tg == 0) {
                out[rowbase + rA] = dA;
                out[rowbase + rB] = dB;
            }
        }
        iid_hold = iid_next;
        __syncwarp();
    }
}

extern "C" void kernel_launch(void* const* d_in, const int* in_sizes, int n_in,
                              void* d_out, int out_size) {
    const int*   user_ids   = (const int*)d_in[0];
    const int*   item_ids   = (const int*)d_in[1];
    const float* user_table = (const float*)d_in[2];
    const float* item_table = (const float*)d_in[3];
    const float* uW1 = (const float*)d_in[4];
    const float* ub1 = (const float*)d_in[5];
    const float* uW2 = (const float*)d_in[6];
    const float* ub2 = (const float*)d_in[7];
    const float* iW1 = (const float*)d_in[8];
    const float* ib1 = (const float*)d_in[9];
    const float* iW2 = (const float*)d_in[10];
    const float* ib2 = (const float*)d_in[11];
    float* out = (float*)d_out;

    cudaFuncSetAttribute(twotower_kernel, cudaFuncAttributeMaxDynamicSharedMemorySize, SMEM_TOTAL);
    twotower_kernel<<<NCTAS, THREADS, SMEM_TOTAL>>>(
        user_ids, item_ids, user_table, item_table,
        uW1, ub1, uW2, ub2, iW1, ib1, iW2, ib2, out);
}